// round 6
// baseline (speedup 1.0000x reference)
#include <cuda_runtime.h>
#include <cuda_fp16.h>
#include <math.h>
#include <stdint.h>
#include <mma.h>

using namespace nvcuda;

#define BS    4096
#define NSLOT 32
#define D     256

// Scratch (device globals), fp16.
__device__ __half g_query[(size_t)NSLOT * BS * D];
__device__ __half g_keyp [(size_t)NSLOT * BS * D];
__device__ __half g_value[(size_t)NSLOT * BS * D];
__device__ __half g_wh   [(size_t)96 * D * D];     // pre-converted weights, [gemm][k][n]

// ---------------------------------------------------------------------------
// Phase 0: convert weights fp32 -> fp16, in proj's gemm order:
//   y < 32        -> qw[y]
//   y >= 32       -> s=(y-32)>>1 ; type=(y-32)&1 ; 0 -> kw[s], 1 -> vw[s]
// ---------------------------------------------------------------------------
__global__ __launch_bounds__(256) void convert_w(
    const float* __restrict__ qw,
    const float* __restrict__ kw,
    const float* __restrict__ vw)
{
    const int y = blockIdx.y;
    const float* W;
    if (y < 32) W = qw + (size_t)y * D * D;
    else {
        const int s = (y - 32) >> 1;
        W = (((y - 32) & 1) == 0 ? kw : vw) + (size_t)s * D * D;
    }
    __half* dst = g_wh + (size_t)y * D * D;
    const int i = (blockIdx.x * 256 + threadIdx.x) * 4;   // 4 floats/thread
    const float4 v = *(const float4*)&W[i];
    __half2 h0 = __floats2half2_rn(v.x, v.y);
    __half2 h1 = __floats2half2_rn(v.z, v.w);
    *(uint2*)&dst[i] = make_uint2(*(uint32_t*)&h0, *(uint32_t*)&h1);
}

// ---------------------------------------------------------------------------
// Phase 1: 96 GEMMs C[4096,256] = X @ W, fp16 HMMA.
// grid (32 m-tiles, 96 gemms), block 512 (16 warps, 4m x 4n; warp tile 32x64).
// CTA tile 128x256 (full N -> X converted once). K-chunk 32, double-buffered.
// ---------------------------------------------------------------------------
#define A_LD  40                          // halfs: 32 + 8
#define B_LD  264                         // halfs: 256 + 8
#define ASZ   (128 * A_LD)
#define BSZ   (32 * B_LD)
#define STG   (ASZ + BSZ)                 // 13568 halfs
#define PROJ_SMEM_BYTES (2 * STG * (int)sizeof(__half))   // 54272 B

__global__ __launch_bounds__(512, 1) void proj_wmma(
    const float* __restrict__ q,
    const float* __restrict__ k)
{
    extern __shared__ __align__(16) __half smh[];

    const int tid  = threadIdx.x;
    const int wid  = tid >> 5;
    const int lane = tid & 31;
    const int wm   = wid >> 2;            // 0..3 -> 32-row slab
    const int wn   = wid & 3;             // 0..3 -> 64-col slab
    const int m0   = blockIdx.x * 128;
    const int y    = blockIdx.y;

    const float* X; __half* C;
    if (y < 32) { X = q + (size_t)y * BS * D; C = g_query + (size_t)y * BS * D; }
    else {
        const int s = (y - 32) >> 1;
        X = k + (size_t)s * BS * D;
        C = (((y - 32) & 1) == 0 ? g_keyp : g_value) + (size_t)s * BS * D;
    }
    const __half* W = g_wh + (size_t)y * D * D;

    // Staging indices
    const int a_row = tid >> 2;           // 0..127
    const int a_c8  = (tid & 3) * 8;      // 8 floats along k
    const int b_kk  = tid >> 4;           // 0..31
    const int b_n16 = (tid & 15) * 16;    // 16 halfs along n

    float4 ra0, ra1;
    uint4  rb0, rb1;

    auto load_regs = [&](int c) {
        const float* ap = &X[(size_t)(m0 + a_row) * D + c * 32 + a_c8];
        ra0 = *(const float4*)ap;
        ra1 = *(const float4*)(ap + 4);
        const __half* bp = &W[(size_t)(c * 32 + b_kk) * D + b_n16];
        rb0 = *(const uint4*)bp;
        rb1 = *(const uint4*)(bp + 8);
    };
    auto store_smem = [&](int buf) {
        __half* a_s = smh + buf * STG;
        __half* b_s = a_s + ASZ;
        __half2 h[4];
        h[0] = __floats2half2_rn(ra0.x, ra0.y);
        h[1] = __floats2half2_rn(ra0.z, ra0.w);
        h[2] = __floats2half2_rn(ra1.x, ra1.y);
        h[3] = __floats2half2_rn(ra1.z, ra1.w);
        *(uint4*)&a_s[a_row * A_LD + a_c8] = *(uint4*)&h[0];
        *(uint4*)&b_s[b_kk * B_LD + b_n16]     = rb0;
        *(uint4*)&b_s[b_kk * B_LD + b_n16 + 8] = rb1;
    };

    wmma::fragment<wmma::accumulator, 16, 16, 16, float> cf[2][4];
#pragma unroll
    for (int i = 0; i < 2; i++)
#pragma unroll
        for (int j = 0; j < 4; j++) wmma::fill_fragment(cf[i][j], 0.0f);

    load_regs(0);
    store_smem(0);
    __syncthreads();

    for (int c = 0; c < 8; c++) {
        if (c < 7) load_regs(c + 1);

        const int buf = c & 1;
        const __half* a_s = smh + buf * STG;
        const __half* b_s = a_s + ASZ;
#pragma unroll
        for (int ks = 0; ks < 2; ks++) {
            wmma::fragment<wmma::matrix_a, 16, 16, 16, __half, wmma::row_major> af[2];
            wmma::fragment<wmma::matrix_b, 16, 16, 16, __half, wmma::row_major> bf[4];
#pragma unroll
            for (int i = 0; i < 2; i++)
                wmma::load_matrix_sync(af[i], a_s + (wm * 32 + 16 * i) * A_LD + ks * 16, A_LD);
#pragma unroll
            for (int j = 0; j < 4; j++)
                wmma::load_matrix_sync(bf[j], b_s + (ks * 16) * B_LD + wn * 64 + 16 * j, B_LD);
#pragma unroll
            for (int i = 0; i < 2; i++)
#pragma unroll
                for (int j = 0; j < 4; j++)
                    wmma::mma_sync(cf[i][j], af[i], bf[j], cf[i][j]);
        }

        if (c < 7) store_smem((c + 1) & 1);
        __syncthreads();
    }

    // Epilogue: per-warp 16x20 fp32 smem buffer -> fp16 gmem
    float* stg = reinterpret_cast<float*>(smh) + wid * (16 * 20);
    const int er = lane >> 1;
    const int ec = (lane & 1) * 8;
#pragma unroll
    for (int i = 0; i < 2; i++) {
#pragma unroll
        for (int j = 0; j < 4; j++) {
            wmma::store_matrix_sync(stg, cf[i][j], 20, wmma::mem_row_major);
            __syncwarp();
            __half2 h[4];
#pragma unroll
            for (int t = 0; t < 4; t++)
                h[t] = __floats2half2_rn(stg[er * 20 + ec + 2 * t], stg[er * 20 + ec + 2 * t + 1]);
            *(uint4*)&C[(size_t)(m0 + wm * 32 + 16 * i + er) * D + wn * 64 + 16 * j + ec] =
                *(uint4*)&h[0];
            __syncwarp();
        }
    }
}

// ---------------------------------------------------------------------------
// Phase 2: per-batch attention on tensor cores (unchanged from round 5).
// ---------------------------------------------------------------------------
#define QK_LD 264
#define LG_LD 36
#define P_LD  40
#define ATTN_SMEM_BYTES ((3 * 32 * QK_LD) * 2 + (2 * 32 * LG_LD) * 4 + (32 * P_LD) * 2)

__global__ __launch_bounds__(256) void attn_tc(float* __restrict__ out)
{
    extern __shared__ __align__(16) __half smem_h[];
    __half* qh = smem_h;
    __half* kh = qh + 32 * QK_LD;
    __half* vh = kh + 32 * QK_LD;
    float*  lg = (float*)(vh + 32 * QK_LD);
    __half* ph = (__half*)(lg + 2 * 32 * LG_LD);

    const int b   = blockIdx.x;
    const int tid = threadIdx.x;
    const int wid = tid >> 5;

#pragma unroll
    for (int p = 0; p < 4; p++) {
        const int idx = p * 256 + tid;
        const int n  = idx >> 5;
        const int a8 = (idx & 31) * 8;
        const size_t g = (size_t)n * BS * D + (size_t)b * D + a8;
        *(uint4*)&qh[n * QK_LD + a8] = *(const uint4*)&g_query[g];
        *(uint4*)&kh[n * QK_LD + a8] = *(const uint4*)&g_keyp[g];
        *(uint4*)&vh[n * QK_LD + a8] = *(const uint4*)&g_value[g];
    }
    __syncthreads();

    {
        const int khalf = wid >> 2;
        const int nt = (wid >> 1) & 1;
        const int mt = wid & 1;
        wmma::fragment<wmma::accumulator, 16, 16, 16, float> acc;
        wmma::fill_fragment(acc, 0.0f);
#pragma unroll
        for (int ks = 0; ks < 8; ks++) {
            const int k0 = khalf * 128 + ks * 16;
            wmma::fragment<wmma::matrix_a, 16, 16, 16, __half, wmma::row_major> af;
            wmma::fragment<wmma::matrix_b, 16, 16, 16, __half, wmma::col_major> bf;
            wmma::load_matrix_sync(af, qh + (nt * 16) * QK_LD + k0, QK_LD);
            wmma::load_matrix_sync(bf, kh + (mt * 16) * QK_LD + k0, QK_LD);
            wmma::mma_sync(acc, af, bf, acc);
        }
        wmma::store_matrix_sync(lg + khalf * 32 * LG_LD + (nt * 16) * LG_LD + mt * 16,
                                acc, LG_LD, wmma::mem_row_major);
    }
    __syncthreads();

    if (tid < 32) {
        const float* l0 = lg + tid * LG_LD;
        const float* l1 = lg + 32 * LG_LD + tid * LG_LD;
        float x[32];
        float mx = -1e30f;
#pragma unroll
        for (int m = 0; m < 32; m++) {
            x[m] = l0[m] + l1[m];
            mx = fmaxf(mx, x[m]);
        }
        float s = 0.0f;
#pragma unroll
        for (int m = 0; m < 32; m++) {
            x[m] = expf((x[m] - mx) * (1.0f / 16.0f));
            s += x[m];
        }
        const float inv = 1.0f / s;
#pragma unroll
        for (int m = 0; m < 32; m += 2)
            *(__half2*)&ph[tid * P_LD + m] = __floats2half2_rn(x[m] * inv, x[m + 1] * inv);
    }
    __syncthreads();

    {
        const int mt2 = wid >> 2;
        const int oc  = wid & 3;
        wmma::fragment<wmma::accumulator, 16, 16, 16, float> acc[4];
#pragma unroll
        for (int j = 0; j < 4; j++) wmma::fill_fragment(acc[j], 0.0f);
#pragma unroll
        for (int ks = 0; ks < 2; ks++) {
            wmma::fragment<wmma::matrix_a, 16, 16, 16, __half, wmma::row_major> af;
            wmma::load_matrix_sync(af, ph + (mt2 * 16) * P_LD + ks * 16, P_LD);
#pragma unroll
            for (int j = 0; j < 4; j++) {
                wmma::fragment<wmma::matrix_b, 16, 16, 16, __half, wmma::row_major> bf;
                wmma::load_matrix_sync(bf, vh + (ks * 16) * QK_LD + oc * 64 + j * 16, QK_LD);
                wmma::mma_sync(acc[j], af, bf, acc[j]);
            }
        }
#pragma unroll
        for (int j = 0; j < 4; j++) {
            float* dst = out + (size_t)(mt2 * 16) * BS * D + (size_t)b * D + oc * 64 + j * 16;
            wmma::store_matrix_sync(dst, acc[j], (unsigned)(BS * D), wmma::mem_row_major);
        }
    }
}

// ---------------------------------------------------------------------------
extern "C" void kernel_launch(void* const* d_in, const int* in_sizes, int n_in,
                              void* d_out, int out_size)
{
    const float* q  = (const float*)d_in[0];
    const float* k  = (const float*)d_in[1];
    const float* qw = (const float*)d_in[2];
    const float* kw = (const float*)d_in[3];
    const float* vw = (const float*)d_in[4];
    float* out = (float*)d_out;

    (void)in_sizes; (void)n_in; (void)out_size;

    // Phase 0: weight conversion (once per launch; ~10us)
    dim3 gw(64, 96);
    convert_w<<<gw, 256>>>(qw, kw, vw);

    // Phase 1: projections
    cudaFuncSetAttribute(proj_wmma, cudaFuncAttributeMaxDynamicSharedMemorySize, PROJ_SMEM_BYTES);
    dim3 grid1(32, 96);
    proj_wmma<<<grid1, 512, PROJ_SMEM_BYTES>>>(q, k);

    // Phase 2: attention
    cudaFuncSetAttribute(attn_tc, cudaFuncAttributeMaxDynamicSharedMemorySize, ATTN_SMEM_BYTES);
    attn_tc<<<BS, 256, ATTN_SMEM_BYTES>>>(out);
}

// round 7
// speedup vs baseline: 1.0911x; 1.0911x over previous
#include <cuda_runtime.h>
#include <cuda_fp16.h>
#include <math.h>
#include <stdint.h>
#include <mma.h>

using namespace nvcuda;

#define BS    4096
#define NSLOT 32
#define D     256

// Scratch (device globals), fp16.
__device__ __half g_query[(size_t)NSLOT * BS * D];
__device__ __half g_keyp [(size_t)NSLOT * BS * D];
__device__ __half g_value[(size_t)NSLOT * BS * D];
__device__ __half g_wh   [(size_t)96 * D * D];     // pre-converted weights [gemm][k][n]

// ---------------------------------------------------------------------------
// Phase 0: weights fp32 -> fp16 in proj gemm order:
//   y < 32 -> qw[y];  y >= 32 -> s=(y-32)>>1, even->kw[s], odd->vw[s]
// ---------------------------------------------------------------------------
__global__ __launch_bounds__(256) void convert_w(
    const float* __restrict__ qw,
    const float* __restrict__ kw,
    const float* __restrict__ vw)
{
    const int y = blockIdx.y;
    const float* W;
    if (y < 32) W = qw + (size_t)y * D * D;
    else {
        const int s = (y - 32) >> 1;
        W = (((y - 32) & 1) == 0 ? kw : vw) + (size_t)s * D * D;
    }
    __half* dst = g_wh + (size_t)y * D * D;
    const int i = (blockIdx.x * 256 + threadIdx.x) * 4;
    const float4 v = *(const float4*)&W[i];
    __half2 h0 = __floats2half2_rn(v.x, v.y);
    __half2 h1 = __floats2half2_rn(v.z, v.w);
    *(uint2*)&dst[i] = make_uint2(*(uint32_t*)&h0, *(uint32_t*)&h1);
}

// ---------------------------------------------------------------------------
// Phase 1: 96 GEMMs C[4096,256] = X @ W, fp16 HMMA.
// grid (2 n-tiles, 32 m-tiles, 96 gemms), block 256 (8 warps 2m x 4n),
// CTA tile 128x128, K-chunk 32, double-buffered smem, 2 CTAs/SM.
// A: fp32 gmem -> cvt -> fp16 smem.  B: fp16 gmem (pre-converted) -> smem copy.
// ---------------------------------------------------------------------------
#define A_LD  40                          // 32 + 8
#define B_LD  136                         // 128 + 8
#define ASZ   (128 * A_LD)
#define BSZ   (32 * B_LD)
#define STG   (ASZ + BSZ)                 // 9472 halfs = 18944 B
#define PROJ_SMEM_BYTES (2 * STG * (int)sizeof(__half))   // 37888 B

__global__ __launch_bounds__(256, 2) void proj_wmma(
    const float* __restrict__ q,
    const float* __restrict__ k)
{
    extern __shared__ __align__(16) __half smh[];

    const int tid  = threadIdx.x;
    const int wid  = tid >> 5;
    const int lane = tid & 31;
    const int wm   = wid >> 2;            // 0..1 (64 rows)
    const int wn   = wid & 3;             // 0..3 (32 cols)
    const int n0   = blockIdx.x * 128;
    const int m0   = blockIdx.y * 128;
    const int y    = blockIdx.z;

    const float* X; __half* C;
    if (y < 32) { X = q + (size_t)y * BS * D; C = g_query + (size_t)y * BS * D; }
    else {
        const int s = (y - 32) >> 1;
        X = k + (size_t)s * BS * D;
        C = (((y - 32) & 1) == 0 ? g_keyp : g_value) + (size_t)s * BS * D;
    }
    const __half* W = g_wh + (size_t)y * D * D;

    // Staging indices
    const int a_row = tid >> 3;           // 0..31 (+32p)
    const int a_c4  = (tid & 7) * 4;      // k offset
    const int b_kk  = tid >> 4;           // 0..15 (+16)
    const int b_n8  = (tid & 15) * 8;     // n offset (8 halfs)

    float4 ra[4];
    uint4  rb[2];

    auto load_regs = [&](int c) {
#pragma unroll
        for (int p = 0; p < 4; p++)
            ra[p] = *(const float4*)&X[(size_t)(m0 + a_row + 32 * p) * D + c * 32 + a_c4];
#pragma unroll
        for (int p = 0; p < 2; p++)
            rb[p] = *(const uint4*)&W[(size_t)(c * 32 + b_kk + 16 * p) * D + n0 + b_n8];
    };
    auto store_smem = [&](int buf) {
        __half* a_s = smh + buf * STG;
        __half* b_s = a_s + ASZ;
#pragma unroll
        for (int p = 0; p < 4; p++) {
            __half2 h0 = __floats2half2_rn(ra[p].x, ra[p].y);
            __half2 h1 = __floats2half2_rn(ra[p].z, ra[p].w);
            *(__half2*)&a_s[(a_row + 32 * p) * A_LD + a_c4]     = h0;
            *(__half2*)&a_s[(a_row + 32 * p) * A_LD + a_c4 + 2] = h1;
        }
#pragma unroll
        for (int p = 0; p < 2; p++)
            *(uint4*)&b_s[(b_kk + 16 * p) * B_LD + b_n8] = rb[p];
    };

    wmma::fragment<wmma::accumulator, 16, 16, 16, float> cf[4][2];
#pragma unroll
    for (int i = 0; i < 4; i++)
#pragma unroll
        for (int j = 0; j < 2; j++) wmma::fill_fragment(cf[i][j], 0.0f);

    load_regs(0);
    store_smem(0);
    __syncthreads();

    for (int c = 0; c < 8; c++) {
        if (c < 7) load_regs(c + 1);

        const int buf = c & 1;
        const __half* a_s = smh + buf * STG;
        const __half* b_s = a_s + ASZ;
#pragma unroll
        for (int ks = 0; ks < 2; ks++) {
            wmma::fragment<wmma::matrix_a, 16, 16, 16, __half, wmma::row_major> af[4];
            wmma::fragment<wmma::matrix_b, 16, 16, 16, __half, wmma::row_major> bf[2];
#pragma unroll
            for (int i = 0; i < 4; i++)
                wmma::load_matrix_sync(af[i], a_s + (wm * 64 + 16 * i) * A_LD + ks * 16, A_LD);
#pragma unroll
            for (int j = 0; j < 2; j++)
                wmma::load_matrix_sync(bf[j], b_s + (ks * 16) * B_LD + wn * 32 + 16 * j, B_LD);
#pragma unroll
            for (int i = 0; i < 4; i++)
#pragma unroll
                for (int j = 0; j < 2; j++)
                    wmma::mma_sync(cf[i][j], af[i], bf[j], cf[i][j]);
        }

        if (c < 7) store_smem((c + 1) & 1);
        __syncthreads();
    }

    // Epilogue: per-warp 16x20 fp32 buffer -> fp16 gmem
    float* stg = reinterpret_cast<float*>(smh) + wid * (16 * 20);
    const int er = lane >> 1;
    const int ec = (lane & 1) * 8;
#pragma unroll
    for (int i = 0; i < 4; i++) {
#pragma unroll
        for (int j = 0; j < 2; j++) {
            wmma::store_matrix_sync(stg, cf[i][j], 20, wmma::mem_row_major);
            __syncwarp();
            __half2 h[4];
#pragma unroll
            for (int t = 0; t < 4; t++)
                h[t] = __floats2half2_rn(stg[er * 20 + ec + 2 * t], stg[er * 20 + ec + 2 * t + 1]);
            *(uint4*)&C[(size_t)(m0 + wm * 64 + 16 * i + er) * D + n0 + wn * 32 + 16 * j + ec] =
                *(uint4*)&h[0];
            __syncwarp();
        }
    }
}

// ---------------------------------------------------------------------------
// Phase 2: per-batch attention on tensor cores (round-5 version, proven 67us).
// ---------------------------------------------------------------------------
#define QK_LD 264
#define LG_LD 36
#define P_LD  40
#define ATTN_SMEM_BYTES ((3 * 32 * QK_LD) * 2 + (2 * 32 * LG_LD) * 4 + (32 * P_LD) * 2)

__global__ __launch_bounds__(256) void attn_tc(float* __restrict__ out)
{
    extern __shared__ __align__(16) __half smem_h[];
    __half* qh = smem_h;
    __half* kh = qh + 32 * QK_LD;
    __half* vh = kh + 32 * QK_LD;
    float*  lg = (float*)(vh + 32 * QK_LD);
    __half* ph = (__half*)(lg + 2 * 32 * LG_LD);

    const int b   = blockIdx.x;
    const int tid = threadIdx.x;
    const int wid = tid >> 5;

#pragma unroll
    for (int p = 0; p < 4; p++) {
        const int idx = p * 256 + tid;
        const int n  = idx >> 5;
        const int a8 = (idx & 31) * 8;
        const size_t g = (size_t)n * BS * D + (size_t)b * D + a8;
        *(uint4*)&qh[n * QK_LD + a8] = *(const uint4*)&g_query[g];
        *(uint4*)&kh[n * QK_LD + a8] = *(const uint4*)&g_keyp[g];
        *(uint4*)&vh[n * QK_LD + a8] = *(const uint4*)&g_value[g];
    }
    __syncthreads();

    {
        const int khalf = wid >> 2;
        const int nt = (wid >> 1) & 1;
        const int mt = wid & 1;
        wmma::fragment<wmma::accumulator, 16, 16, 16, float> acc;
        wmma::fill_fragment(acc, 0.0f);
#pragma unroll
        for (int ks = 0; ks < 8; ks++) {
            const int k0 = khalf * 128 + ks * 16;
            wmma::fragment<wmma::matrix_a, 16, 16, 16, __half, wmma::row_major> af;
            wmma::fragment<wmma::matrix_b, 16, 16, 16, __half, wmma::col_major> bf;
            wmma::load_matrix_sync(af, qh + (nt * 16) * QK_LD + k0, QK_LD);
            wmma::load_matrix_sync(bf, kh + (mt * 16) * QK_LD + k0, QK_LD);
            wmma::mma_sync(acc, af, bf, acc);
        }
        wmma::store_matrix_sync(lg + khalf * 32 * LG_LD + (nt * 16) * LG_LD + mt * 16,
                                acc, LG_LD, wmma::mem_row_major);
    }
    __syncthreads();

    if (tid < 32) {
        const float* l0 = lg + tid * LG_LD;
        const float* l1 = lg + 32 * LG_LD + tid * LG_LD;
        float x[32];
        float mx = -1e30f;
#pragma unroll
        for (int m = 0; m < 32; m++) {
            x[m] = l0[m] + l1[m];
            mx = fmaxf(mx, x[m]);
        }
        float s = 0.0f;
#pragma unroll
        for (int m = 0; m < 32; m++) {
            x[m] = expf((x[m] - mx) * (1.0f / 16.0f));
            s += x[m];
        }
        const float inv = 1.0f / s;
#pragma unroll
        for (int m = 0; m < 32; m += 2)
            *(__half2*)&ph[tid * P_LD + m] = __floats2half2_rn(x[m] * inv, x[m + 1] * inv);
    }
    __syncthreads();

    {
        const int mt2 = wid >> 2;
        const int oc  = wid & 3;
        wmma::fragment<wmma::accumulator, 16, 16, 16, float> acc[4];
#pragma unroll
        for (int j = 0; j < 4; j++) wmma::fill_fragment(acc[j], 0.0f);
#pragma unroll
        for (int ks = 0; ks < 2; ks++) {
            wmma::fragment<wmma::matrix_a, 16, 16, 16, __half, wmma::row_major> af;
            wmma::load_matrix_sync(af, ph + (mt2 * 16) * P_LD + ks * 16, P_LD);
#pragma unroll
            for (int j = 0; j < 4; j++) {
                wmma::fragment<wmma::matrix_b, 16, 16, 16, __half, wmma::row_major> bf;
                wmma::load_matrix_sync(bf, vh + (ks * 16) * QK_LD + oc * 64 + j * 16, QK_LD);
                wmma::mma_sync(acc[j], af, bf, acc[j]);
            }
        }
#pragma unroll
        for (int j = 0; j < 4; j++) {
            float* dst = out + (size_t)(mt2 * 16) * BS * D + (size_t)b * D + oc * 64 + j * 16;
            wmma::store_matrix_sync(dst, acc[j], (unsigned)(BS * D), wmma::mem_row_major);
        }
    }
}

// ---------------------------------------------------------------------------
extern "C" void kernel_launch(void* const* d_in, const int* in_sizes, int n_in,
                              void* d_out, int out_size)
{
    const float* q  = (const float*)d_in[0];
    const float* k  = (const float*)d_in[1];
    const float* qw = (const float*)d_in[2];
    const float* kw = (const float*)d_in[3];
    const float* vw = (const float*)d_in[4];
    float* out = (float*)d_out;

    (void)in_sizes; (void)n_in; (void)out_size;

    dim3 gw(64, 96);
    convert_w<<<gw, 256>>>(qw, kw, vw);

    cudaFuncSetAttribute(proj_wmma, cudaFuncAttributeMaxDynamicSharedMemorySize, PROJ_SMEM_BYTES);
    dim3 grid1(2, 32, 96);
    proj_wmma<<<grid1, 256, PROJ_SMEM_BYTES>>>(q, k);

    cudaFuncSetAttribute(attn_tc, cudaFuncAttributeMaxDynamicSharedMemorySize, ATTN_SMEM_BYTES);
    attn_tc<<<BS, 256, ATTN_SMEM_BYTES>>>(out);
}